// round 14
// baseline (speedup 1.0000x reference)
#include <cuda_runtime.h>

// Neural 2D min-sum BP decoder, GB300 sm_103a.
// v6 = v5 (2-codeword float2 packing + layer-0 identity relabel + register-
//      resident layer 0 + minsum6 sign-XOR/abs-modifier trim) with:
//      (a) re1/re2 packed into one 32-bit register per variable (16-bit halves)
//      (b) variable-phase random loads batched 8-wide (16 LDS.64 in flight)
//          — ptxas cannot reorder the subsequent random stores above them,
//          so the source-level batch is preserved in SASS.
//
// Internal variable label u == layer-0 edge slot (u's layer-0 check = u/2).
// Thread tid owns checks c = tid + kc*1024 (kc<4) and variables u = 2c+j.
// Layer-0 messages live in registers across all T iterations. SMEM holds
// layers 1,2 (128KB float2[(cwA,cwB)] per edge) + llr as float4 per check
// (64KB) = 192KB.
//
// Check min-sum: prefix/suffix exclusive mins (bit-identical to reference's
// argmin/min2 tie rule; layer-0 edges are positions 0,1 = lowest edge indices,
// preserving first-occurrence ties) + sign-bit XOR with exact zero guard
// (jnp.sign(0)=0 => any zero operand zeroes the whole check's c2v: beta:=0).

#define NV 8192
#define MC 4096
#define EE 24576
#define NTHREADS 1024
#define CPT (MC / NTHREADS)   // 4 checks/thread -> 8 variables/thread

__device__ __forceinline__ void minsum6(float x[6], float bt) {
    unsigned u0 = __float_as_uint(x[0]);
    unsigned u1 = __float_as_uint(x[1]);
    unsigned u2 = __float_as_uint(x[2]);
    unsigned u3 = __float_as_uint(x[3]);
    unsigned u4 = __float_as_uint(x[4]);
    unsigned u5 = __float_as_uint(x[5]);
    unsigned sxall = u0 ^ u1 ^ u2 ^ u3 ^ u4 ^ u5;      // sign product in bit 31

    // magnitudes enter the min network as |src| modifiers on FMNMX (no AND ops)
    float pre1 = fminf(fabsf(x[0]), fabsf(x[1]));
    float pre2 = fminf(pre1, fabsf(x[2]));
    float pre3 = fminf(pre2, fabsf(x[3]));
    float pre4 = fminf(pre3, fabsf(x[4]));
    float suf4 = fminf(fabsf(x[5]), fabsf(x[4]));
    float suf3 = fminf(suf4, fabsf(x[3]));
    float suf2 = fminf(suf3, fabsf(x[2]));
    float suf1 = fminf(suf2, fabsf(x[1]));
    float ex0 = suf1;
    float ex1 = fminf(fabsf(x[0]), suf2);
    float ex2 = fminf(pre1, suf3);
    float ex3 = fminf(pre2, suf4);
    float ex4 = fminf(pre3, fabsf(x[5]));
    float ex5 = pre4;
    float min_all = fminf(pre4, fabsf(x[5]));
    float btz = (min_all == 0.0f) ? 0.0f : bt;          // exact sign(0)=0 semantics

    // out_j = (btz * ex_j) with sign flipped by (sxall ^ u_j) bit 31
    x[0] = __uint_as_float(__float_as_uint(btz * ex0) ^ ((sxall ^ u0) & 0x80000000u));
    x[1] = __uint_as_float(__float_as_uint(btz * ex1) ^ ((sxall ^ u1) & 0x80000000u));
    x[2] = __uint_as_float(__float_as_uint(btz * ex2) ^ ((sxall ^ u2) & 0x80000000u));
    x[3] = __uint_as_float(__float_as_uint(btz * ex3) ^ ((sxall ^ u3) & 0x80000000u));
    x[4] = __uint_as_float(__float_as_uint(btz * ex4) ^ ((sxall ^ u4) & 0x80000000u));
    x[5] = __uint_as_float(__float_as_uint(btz * ex5) ^ ((sxall ^ u5) & 0x80000000u));
}

__global__ void __launch_bounds__(NTHREADS, 1)
bp_kernel(const float* __restrict__ llr_g,
          const int* __restrict__ edge_v,
          const float* __restrict__ beta,
          const float* __restrict__ alpha,
          int T, int B, float* __restrict__ out)
{
    extern __shared__ float smemf[];
    // persistent layout (floats):
    //   [0, 4NV)    : p2 = float2[2NV]  layer1 block [0,NV), layer2 [NV,2NV)
    //   [4NV, 6NV)  : llr4 = float4[MC] per check: (LA(2c),LB(2c),LA(2c+1),LB(2c+1))
    float2* p2    = (float2*)smemf;
    float4* p4l1  = (float4*)smemf;               // index c in [0, MC)
    float4* p4l2  = (float4*)(smemf + 2 * NV);    // index c
    float4* llr4  = (float4*)(smemf + 4 * NV);    // index c
    // transient init overlays inside the p2 region (dead before p2 is written):
    int*    invtmp = (int*)smemf;                 // [2NV] inverse perms layers 1,2
    float2* lstv   = (float2*)(smemf + 2 * NV);   // [NV] llr staged by original v

    const int tid = threadIdx.x;
    const int b0  = blockIdx.x * 2;
    int       b1  = b0 + 1;
    const bool hasB = (b1 < B);
    if (!hasB) b1 = b0;

    const float* lA = llr_g + (size_t)b0 * NV;
    const float* lB = llr_g + (size_t)b1 * NV;

    // ---- init step 1: stage llr by original v; build layer-1/2 inverse perms ----
#pragma unroll
    for (int k = 0; k < NV / NTHREADS; ++k) {
        int v = tid + k * NTHREADS;
        lstv[v] = make_float2(__ldg(&lA[v]), __ldg(&lB[v]));
    }
#pragma unroll
    for (int k = 0; k < 2 * NV / NTHREADS; ++k) {
        int e = tid + k * NTHREADS;               // e in [0,2NV) -> edge NV+e
        int blk = (e >> 13) << 13;                // 0 (layer1) or NV (layer2)
        invtmp[blk + __ldg(&edge_v[NV + e])] = e & (NV - 1);
    }
    __syncthreads();

    // ---- init step 2: per owned variable u = 2*(tid+kc*1024)+j ----
    // pk12[idx] = re1 | (re2 << 16); re1 in [0,NV), re2 in [NV,2NV) (fits u16)
    unsigned pk12[2 * CPT];
    float    v0a[2 * CPT], v0b[2 * CPT];          // layer-0 message registers
#pragma unroll
    for (int kc = 0; kc < CPT; ++kc) {
        int c = tid + kc * NTHREADS;
        float4 Lq;
#pragma unroll
        for (int j = 0; j < 2; ++j) {
            int idx = kc * 2 + j;
            int u = 2 * c + j;
            int v = __ldg(&edge_v[u]);            // original variable of slot u
            unsigned r1 = (unsigned)invtmp[v];            // layer1 slot
            unsigned r2 = (unsigned)(NV + invtmp[NV + v]);// layer2 slot (absolute)
            pk12[idx] = r1 | (r2 << 16);
            float2 L = lstv[v];
            v0a[idx] = L.x;  v0b[idx] = L.y;      // v2c layer-0 init = llr
            if (j == 0) { Lq.x = L.x; Lq.y = L.y; }
            else        { Lq.z = L.x; Lq.w = L.y; }
        }
        llr4[c] = Lq;                             // [4NV,6NV): disjoint from overlays
    }
    __syncthreads();                              // overlays dead after this

    // ---- init step 3: v2c init for layers 1,2 (random scatter) ----
#pragma unroll
    for (int idx = 0; idx < 2 * CPT; ++idx) {
        float2 f = make_float2(v0a[idx], v0b[idx]);
        p2[pk12[idx] & 0xFFFFu] = f;
        p2[pk12[idx] >> 16]     = f;
    }
    __syncthreads();

    for (int t = 0; t < T; ++t) {
        const float bt = __ldg(&beta[t]);
        const float at = __ldg(&alpha[t]);

        // -------- check phase: layers 1,2 via smem, layer 0 in registers --------
#pragma unroll
        for (int kc = 0; kc < CPT; ++kc) {
            int c = tid + kc * NTHREADS;
            float4 q1 = p4l1[c];                  // (A_e0,B_e0,A_e1,B_e1) layer1
            float4 q2 = p4l2[c];                  // layer2
            float xa[6] = {v0a[kc*2], v0a[kc*2+1], q1.x, q1.z, q2.x, q2.z};
            float xb[6] = {v0b[kc*2], v0b[kc*2+1], q1.y, q1.w, q2.y, q2.w};
            minsum6(xa, bt);
            minsum6(xb, bt);
            v0a[kc*2] = xa[0];  v0a[kc*2+1] = xa[1];
            v0b[kc*2] = xb[0];  v0b[kc*2+1] = xb[1];
            p4l1[c] = make_float4(xa[2], xb[2], xa[3], xb[3]);
            p4l2[c] = make_float4(xa[4], xb[4], xa[5], xb[5]);
        }
        __syncthreads();

        // -------- variable phase (skipped at t = T-1) --------
        // 8-wide batch: all 16 random LDS.64 issued before any compute/store.
        // Legal: per-thread edge slots are pairwise distinct (exclusive edge
        // ownership); ptxas preserves the order because it cannot prove the
        // random stores don't alias the loads.
        if (t != T - 1) {
            float2 g1[2 * CPT], g2[2 * CPT];
#pragma unroll
            for (int i = 0; i < 2 * CPT; ++i) {
                unsigned pk = pk12[i];
                g1[i] = p2[pk & 0xFFFFu];
                g2[i] = p2[pk >> 16];
            }
#pragma unroll
            for (int kc = 0; kc < CPT; ++kc) {
                float4 Lq = llr4[tid + kc * NTHREADS];   // conflict-free LDS.128
#pragma unroll
                for (int j = 0; j < 2; ++j) {
                    int idx = kc * 2 + j;
                    float2 c1 = g1[idx], c2 = g2[idx];
                    float c0A = v0a[idx], c0B = v0b[idx];
                    float sA = c0A + c1.x + c2.x;
                    float sB = c0B + c1.y + c2.y;
                    float LAv = j ? Lq.z : Lq.x;
                    float LBv = j ? Lq.w : Lq.y;
                    v0a[idx] = fmaf(at, sA - c0A, LAv);
                    v0b[idx] = fmaf(at, sB - c0B, LBv);
                    unsigned pk = pk12[idx];
                    p2[pk & 0xFFFFu] = make_float2(fmaf(at, sA - c1.x, LAv),
                                                   fmaf(at, sB - c1.y, LBv));
                    p2[pk >> 16]     = make_float2(fmaf(at, sA - c2.x, LAv),
                                                   fmaf(at, sB - c2.y, LBv));
                }
            }
            __syncthreads();
        }
    }

    // -------- epilogue: posterior from last c2v, restore original labels --------
    float pa[2 * CPT], pb[2 * CPT];
#pragma unroll
    for (int kc = 0; kc < CPT; ++kc) {
        int c = tid + kc * NTHREADS;
        float4 Lq = llr4[c];
#pragma unroll
        for (int j = 0; j < 2; ++j) {
            int idx = kc * 2 + j;
            unsigned pk = pk12[idx];
            float2 c1 = p2[pk & 0xFFFFu];
            float2 c2 = p2[pk >> 16];
            float LAv = j ? Lq.z : Lq.x;
            float LBv = j ? Lq.w : Lq.y;
            pa[idx] = LAv + (v0a[idx] + c1.x + c2.x);
            pb[idx] = LBv + (v0b[idx] + c1.y + c2.y);
        }
    }
    __syncthreads();                              // all p2 reads done
    float2* st = (float2*)smemf;                  // [NV] by original v (overlay)
#pragma unroll
    for (int kc = 0; kc < CPT; ++kc) {
#pragma unroll
        for (int j = 0; j < 2; ++j) {
            int idx = kc * 2 + j;
            int u = 2 * (tid + kc * NTHREADS) + j;
            st[__ldg(&edge_v[u])] = make_float2(pa[idx], pb[idx]);
        }
    }
    __syncthreads();
    float* outbA = out + (size_t)b0 * NV;
    float* outpA = out + (size_t)B * NV + (size_t)b0 * NV;
    float* outbB = out + (size_t)b1 * NV;
    float* outpB = out + (size_t)B * NV + (size_t)b1 * NV;
#pragma unroll
    for (int k = 0; k < NV / NTHREADS; ++k) {
        int v = tid + k * NTHREADS;
        float2 f = st[v];
        outbA[v] = (f.x < 0.0f) ? 1.0f : 0.0f;
        outpA[v] = f.x;
        if (hasB) {
            outbB[v] = (f.y < 0.0f) ? 1.0f : 0.0f;
            outpB[v] = f.y;
        }
    }
}

extern "C" void kernel_launch(void* const* d_in, const int* in_sizes, int n_in,
                              void* d_out, int out_size) {
    // metadata order: llr [B*N f32], edge_v [E i32], edge_c [E i32] (unused),
    //                 beta [T f32], alpha [T f32]
    const float* llr    = (const float*)d_in[0];
    const int*   edge_v = (const int*)d_in[1];
    const float* beta   = (const float*)d_in[3];
    const float* alpha  = (const float*)d_in[4];

    int B = in_sizes[0] / NV;   // 512
    int T = in_sizes[3];        // 10

    size_t smem_bytes = (size_t)(6 * NV) * sizeof(float); // 192KB
    static int attr_set = 0;
    if (!attr_set) {
        cudaFuncSetAttribute(bp_kernel, cudaFuncAttributeMaxDynamicSharedMemorySize,
                             (int)smem_bytes);
        attr_set = 1;
    }

    int grid = (B + 1) / 2;     // 256
    bp_kernel<<<grid, NTHREADS, smem_bytes>>>(llr, edge_v, beta, alpha, T, B,
                                              (float*)d_out);
}